// round 6
// baseline (speedup 1.0000x reference)
#include <cuda_runtime.h>
#include <cuda_bf16.h>
#include <math.h>
#include <stdint.h>

#define TT 8
#define NNODE 40000
#define FF 256
#define PP 128
#define GG 128
#define HH 128
#define BB 1024
#define NE 640000
#define NNZ (NE + NNODE)

// ------------------------- device scratch -------------------------
__device__ __align__(16) float g_h  [(size_t)NNODE * PP];
__device__ __align__(16) float g_m  [(size_t)NNODE * GG];
__device__ __align__(16) float g_h2 [(size_t)NNODE * GG];
__device__ __align__(16) float g_hc [(size_t)NNODE * GG];
__device__ __align__(16) float g_mc [(size_t)NNODE * GG];
__device__ __align__(16) float g_tgt[(size_t)TT * BB * (2 * GG)];
__device__ __align__(16) float g_gi [(size_t)TT * BB * (3 * HH)];
__device__ __align__(16) float g_gh [(size_t)BB * (3 * HH)];
__device__ __align__(16) float g_gruh[(size_t)BB * HH];
__device__ __align__(16) float g_outs[(size_t)TT * BB * HH];
__device__ __align__(16) float g_val [NNZ];
__device__ __align__(16) float g_dinv[NNODE];
__device__ __align__(16) int   g_col [NNZ];
__device__ __align__(16) int   g_rowptr[NNODE + 1];
__device__ __align__(16) int   g_deg [NNODE];
__device__ __align__(16) int   g_fill[NNODE];
__device__ __align__(16) int   g_src [NE];
__device__ __align__(16) int   g_dst [NE];
__device__ __align__(16) int   g_ti  [BB];
// pruning structures
__device__ __align__(16) int   g_tmask[NNODE];
__device__ __align__(16) int   g_smask[NNODE];
__device__ __align__(16) int   g_snodes[NNODE];
__device__ __align__(16) int   g_sidx [NNODE];
__device__ __align__(16) int   g_tnodes[BB];
__device__ int g_nt;
__device__ int g_ns;
__device__ int g_is64;
// permuted tf32 weights (fragment-linear order)
__device__ __align__(16) uint32_t g_pw  [256 * 128];
__device__ __align__(16) uint32_t g_pw1 [128 * 128];
__device__ __align__(16) uint32_t g_pw2 [128 * 128];
__device__ __align__(16) uint32_t g_pwih[256 * 384];
__device__ __align__(16) uint32_t g_pwhh[128 * 384];

// ------------------------- tf32 helpers -------------------------
__device__ __forceinline__ uint32_t f2tf(float f) {
    uint32_t r;
    asm("cvt.rna.tf32.f32 %0, %1;" : "=r"(r) : "f"(f));
    return r;
}
__device__ __forceinline__ void mma8(float* c, const uint32_t* a, const uint32_t* b) {
    asm volatile(
        "mma.sync.aligned.m16n8k8.row.col.f32.tf32.tf32.f32 "
        "{%0,%1,%2,%3},{%4,%5,%6,%7},{%8,%9},{%0,%1,%2,%3};"
        : "+f"(c[0]), "+f"(c[1]), "+f"(c[2]), "+f"(c[3])
        : "r"(a[0]), "r"(a[1]), "r"(a[2]), "r"(a[3]), "r"(b[0]), "r"(b[1]));
}

// ------------------------- weight permutation to fragment order -------------------------
// out[((nb*K8 + kg)*16 + nt)*64 + lane*2 + j] = tf32(W[k][n]),
//   k = kg*8 + (lane&3) + 4*j,  n = nb*128 + nt*8 + (lane>>2)
template<bool TRANS>
__global__ void k_permB(const float* __restrict__ W, uint32_t* __restrict__ out, int K, int N) {
    int i = blockIdx.x * blockDim.x + threadIdx.x;
    if (i >= K * N) return;
    int tmp = i;
    int j = tmp & 1;       tmp >>= 1;
    int lane = tmp & 31;   tmp >>= 5;
    int nt = tmp & 15;     tmp >>= 4;
    int K8 = K >> 3;
    int kg = tmp % K8;
    int nb = tmp / K8;
    int k = kg * 8 + (lane & 3) + 4 * j;
    int n = nb * 128 + nt * 8 + (lane >> 2);
    float v = TRANS ? W[(size_t)n * K + k] : W[(size_t)k * N + n];
    out[i] = f2tf(v);
}

// ------------------------- TF32 GEMM: C[M,N] = op(A @ B + bias) -------------------------
// CTA 128x128, 8 warps. B panel staged ONCE in dynamic smem (fragment-linear,
// conflict-free LDS.64); A fragments loaded directly from gmem (constant-offset
// LDG.32, fully unrolled -> deep MLP). No in-loop syncthreads.
// ASEL: 0 ext, 1 g_h, 2 g_hc, 3 g_tgt, 4 g_gruh ; CSEL: 1 g_h, 2 g_m, 3 g_mc, 4 g_gi, 5 g_gh
// MSEL: 0 = param M, 1 = g_ns
template<int KTOT, int ASEL, int CSEL, int MSEL, bool RELU, bool BIAS>
__global__ void __launch_bounds__(256) tfgemm(const float* __restrict__ Aext,
                                              const uint32_t* __restrict__ pB,
                                              const float* __restrict__ bias, int Mparam)
{
    extern __shared__ uint32_t Bs[];           // KTOT*128 words
    int M = (MSEL == 1) ? g_ns : Mparam;
    int rowBase = blockIdx.y * 128;
    if (rowBase >= M) return;

    const float* A;
    if constexpr (ASEL == 1)      A = g_h;
    else if constexpr (ASEL == 2) A = g_hc;
    else if constexpr (ASEL == 3) A = g_tgt;
    else if constexpr (ASEL == 4) A = g_gruh;
    else                          A = Aext;
    float* C;
    if constexpr (CSEL == 1)      C = g_h;
    else if constexpr (CSEL == 2) C = g_m;
    else if constexpr (CSEL == 3) C = g_mc;
    else if constexpr (CSEL == 4) C = g_gi;
    else                          C = g_gh;

    const int K8 = KTOT / 8;
    const int N = gridDim.x * 128;
    const int nb = blockIdx.x;
    int tid = threadIdx.x;
    int lane = tid & 31;
    int w = tid >> 5;
    int warpM = w & 3;
    int warpN = w >> 2;

    // stage B panel (contiguous slice of pB for this nb)
    {
        const uint4* src = (const uint4*)(pB + (size_t)nb * KTOT * 128);
        uint4* dst = (uint4*)Bs;
#pragma unroll
        for (int i = 0; i < KTOT / 8; i++)     // KTOT*32 uint4 / 256 threads
            dst[i * 256 + tid] = src[i * 256 + tid];
    }
    __syncthreads();

    float acc[2][8][4];
#pragma unroll
    for (int mt = 0; mt < 2; mt++)
#pragma unroll
        for (int nt = 0; nt < 8; nt++)
#pragma unroll
            for (int q = 0; q < 4; q++) acc[mt][nt][q] = 0.f;

    // A row pointers (clamped: results for OOB rows are discarded in epilogue)
    int r0 = rowBase + warpM * 32 + (lane >> 2);
    int c0 = lane & 3;
    int Mm1 = M - 1;
    const float* pa00 = A + (size_t)(r0      < M ? r0      : Mm1) * KTOT + c0;
    const float* pa01 = A + (size_t)(r0 + 8  < M ? r0 + 8  : Mm1) * KTOT + c0;
    const float* pa10 = A + (size_t)(r0 + 16 < M ? r0 + 16 : Mm1) * KTOT + c0;
    const float* pa11 = A + (size_t)(r0 + 24 < M ? r0 + 24 : Mm1) * KTOT + c0;

#pragma unroll
    for (int kg = 0; kg < K8; kg++) {
        uint32_t af0[4], af1[4];
        af0[0] = f2tf(pa00[kg * 8]);     af0[2] = f2tf(pa00[kg * 8 + 4]);
        af0[1] = f2tf(pa01[kg * 8]);     af0[3] = f2tf(pa01[kg * 8 + 4]);
        af1[0] = f2tf(pa10[kg * 8]);     af1[2] = f2tf(pa10[kg * 8 + 4]);
        af1[1] = f2tf(pa11[kg * 8]);     af1[3] = f2tf(pa11[kg * 8 + 4]);
#pragma unroll
        for (int nt = 0; nt < 8; nt++) {
            int ntg = warpN * 8 + nt;
            uint2 b = *(const uint2*)&Bs[((size_t)kg * 16 + ntg) * 64 + lane * 2];
            uint32_t bb[2] = {b.x, b.y};
            mma8(acc[0][nt], af0, bb);
            mma8(acc[1][nt], af1, bb);
        }
    }

    // epilogue
#pragma unroll
    for (int mt = 0; mt < 2; mt++) {
        int rr0 = rowBase + warpM * 32 + mt * 16 + (lane >> 2);
        int rr1 = rr0 + 8;
#pragma unroll
        for (int nt = 0; nt < 8; nt++) {
            int cb = nb * 128 + warpN * 64 + nt * 8 + (lane & 3) * 2;
            float o0 = acc[mt][nt][0], o1 = acc[mt][nt][1];
            float o2 = acc[mt][nt][2], o3 = acc[mt][nt][3];
            if (BIAS) {
                float b0 = bias[cb], b1 = bias[cb + 1];
                o0 += b0; o1 += b1; o2 += b0; o3 += b1;
            }
            if (RELU) {
                o0 = fmaxf(o0, 0.f); o1 = fmaxf(o1, 0.f);
                o2 = fmaxf(o2, 0.f); o3 = fmaxf(o3, 0.f);
            }
            if (rr0 < M) { float2 s = {o0, o1}; *(float2*)(C + (size_t)rr0 * N + cb) = s; }
            if (rr1 < M) { float2 s = {o2, o3}; *(float2*)(C + (size_t)rr1 * N + cb) = s; }
        }
    }
}

// ------------------------- index dtype detection + conversion -------------------------
__global__ void k_detect(const unsigned int* __restrict__ wdata, int n_elems) {
    __shared__ int bad;
    if (threadIdx.x == 0) bad = 0;
    __syncthreads();
    int limit = n_elems < 4096 ? n_elems : 4096;
    for (int i = threadIdx.x; i < limit; i += blockDim.x)
        if (wdata[2 * i + 1] != 0u) bad = 1;
    __syncthreads();
    if (threadIdx.x == 0) g_is64 = bad ? 0 : 1;
}

__device__ __forceinline__ int clampN(int v) {
    return v < 0 ? 0 : (v >= NNODE ? NNODE - 1 : v);
}

__global__ void k_cvt_edges(const void* __restrict__ ei) {
    int e = blockIdx.x * blockDim.x + threadIdx.x;
    if (e < NE) {
        int s, d;
        if (g_is64) {
            const long long* p = (const long long*)ei;
            s = (int)p[e]; d = (int)p[NE + e];
        } else {
            const int* p = (const int*)ei;
            s = p[e]; d = p[NE + e];
        }
        g_src[e] = clampN(s);
        g_dst[e] = clampN(d);
    }
}

__global__ void k_cvt_ti(const void* __restrict__ ti) {
    int b = blockIdx.x * blockDim.x + threadIdx.x;
    if (b < BB) {
        int v;
        if (g_is64) v = (int)((const long long*)ti)[b];
        else        v = ((const int*)ti)[b];
        g_ti[b] = clampN(v);
    }
}

// ------------------------- graph preprocessing -------------------------
__global__ void k_init_deg() {
    int i = blockIdx.x * blockDim.x + threadIdx.x;
    if (i < NNODE) { g_deg[i] = 1; g_fill[i] = 0; }
    if (i == 0) { g_nt = 0; g_ns = 0; }
}

__global__ void k_deg_edges() {
    int e = blockIdx.x * blockDim.x + threadIdx.x;
    if (e < NE) atomicAdd(&g_deg[g_dst[e]], 1);
}

__global__ void k_dinv() {
    int i = blockIdx.x * blockDim.x + threadIdx.x;
    if (i < NNODE) g_dinv[i] = rsqrtf((float)g_deg[i]);
}

__global__ void k_scan() {
    const int CH = 40;
    int t = threadIdx.x;
    int lane = t & 31, wid = t >> 5;
    int beg = t * CH;
    int sum = 0;
    for (int i = 0; i < CH; i++) {
        int idx = beg + i;
        if (idx < NNODE) sum += g_deg[idx];
    }
    int v = sum;
    for (int o = 1; o < 32; o <<= 1) {
        int u = __shfl_up_sync(0xffffffffu, v, o);
        if (lane >= o) v += u;
    }
    __shared__ int wsum[32];
    if (lane == 31) wsum[wid] = v;
    __syncthreads();
    if (wid == 0) {
        int w = wsum[lane];
        for (int o = 1; o < 32; o <<= 1) {
            int u = __shfl_up_sync(0xffffffffu, w, o);
            if (lane >= o) w += u;
        }
        wsum[lane] = w;
    }
    __syncthreads();
    int run = v - sum + (wid > 0 ? wsum[wid - 1] : 0);
    for (int i = 0; i < CH; i++) {
        int idx = beg + i;
        if (idx < NNODE) {
            g_rowptr[idx] = run;
            run += g_deg[idx];
        }
    }
    if (t == 1023) g_rowptr[NNODE] = run;
}

__global__ void k_selfloop() {
    int n = blockIdx.x * blockDim.x + threadIdx.x;
    if (n < NNODE) {
        int pos = g_rowptr[n];
        g_col[pos] = n;
        float d = g_dinv[n];
        g_val[pos] = d * d;
        g_fill[n] = 1;
    }
}

__global__ void k_fill_edges() {
    int e = blockIdx.x * blockDim.x + threadIdx.x;
    if (e < NE) {
        int s = g_src[e];
        int d = g_dst[e];
        int pos = g_rowptr[d] + atomicAdd(&g_fill[d], 1);
        g_col[pos] = s;
        g_val[pos] = g_dinv[s] * g_dinv[d];
    }
}

// ------------------------- target-neighborhood compaction -------------------------
__global__ void k_clear_masks() {
    int i = blockIdx.x * blockDim.x + threadIdx.x;
    if (i < NNODE) { g_tmask[i] = 0; g_smask[i] = 0; }
}
__global__ void k_mark_t() {
    int b = blockIdx.x * blockDim.x + threadIdx.x;
    if (b < BB) g_tmask[g_ti[b]] = 1;
}
__global__ void k_mark_s() {
    int e = blockIdx.x * blockDim.x + threadIdx.x;
    if (e < NE && g_tmask[g_dst[e]]) g_smask[g_src[e]] = 1;
}
__global__ void k_mark_s2() {
    int n = blockIdx.x * blockDim.x + threadIdx.x;
    if (n < NNODE && g_tmask[n]) g_smask[n] = 1;
}
__global__ void k_compact() {
    int n = blockIdx.x * blockDim.x + threadIdx.x;
    if (n < NNODE) {
        if (g_tmask[n]) g_tnodes[atomicAdd(&g_nt, 1)] = n;
        if (g_smask[n]) {
            int ix = atomicAdd(&g_ns, 1);
            g_snodes[ix] = n;
            g_sidx[n] = ix;
        }
    }
}

// ------------------------- GCN layer-1 aggregation at S nodes only -------------------------
__global__ void k_agg1c(const float* __restrict__ bias)
{
    int warp = (blockIdx.x * blockDim.x + threadIdx.x) >> 5;
    int lane = threadIdx.x & 31;
    if (warp >= g_ns) return;
    int node = g_snodes[warp];
    int s0 = g_rowptr[node], s1 = g_rowptr[node + 1];
    const float4* m4 = (const float4*)g_m;
    float4 acc = make_float4(0.f, 0.f, 0.f, 0.f);
    for (int e = s0; e < s1; e++) {
        float v = g_val[e];
        float4 t = m4[(size_t)g_col[e] * 32 + lane];
        acc.x = fmaf(v, t.x, acc.x); acc.y = fmaf(v, t.y, acc.y);
        acc.z = fmaf(v, t.z, acc.z); acc.w = fmaf(v, t.w, acc.w);
    }
    int c = lane * 4;
    acc.x = fmaxf(acc.x + bias[c + 0], 0.f);
    acc.y = fmaxf(acc.y + bias[c + 1], 0.f);
    acc.z = fmaxf(acc.z + bias[c + 2], 0.f);
    acc.w = fmaxf(acc.w + bias[c + 3], 0.f);
    ((float4*)g_hc)[(size_t)warp * 32 + lane] = acc;     // compact row = warp (s-index)
}

// layer-2 aggregation only over unique target nodes (compact m)
__global__ void k_agg2t(const float* __restrict__ bias)
{
    int warp = (blockIdx.x * blockDim.x + threadIdx.x) >> 5;
    int lane = threadIdx.x & 31;
    if (warp >= g_nt) return;
    int node = g_tnodes[warp];
    int s0 = g_rowptr[node], s1 = g_rowptr[node + 1];
    const float4* m4 = (const float4*)g_mc;
    float4 acc = make_float4(0.f, 0.f, 0.f, 0.f);
    for (int e = s0; e < s1; e++) {
        float v = g_val[e];
        float4 t = m4[(size_t)g_sidx[g_col[e]] * 32 + lane];
        acc.x = fmaf(v, t.x, acc.x); acc.y = fmaf(v, t.y, acc.y);
        acc.z = fmaf(v, t.z, acc.z); acc.w = fmaf(v, t.w, acc.w);
    }
    int c = lane * 4;
    acc.x = fmaxf(acc.x + bias[c + 0], 0.f);
    acc.y = fmaxf(acc.y + bias[c + 1], 0.f);
    acc.z = fmaxf(acc.z + bias[c + 2], 0.f);
    acc.w = fmaxf(acc.w + bias[c + 3], 0.f);
    ((float4*)g_h2)[(size_t)node * 32 + lane] = acc;
}

// ------------------------- gather targets -------------------------
__global__ void k_gather(int t) {
    int b = blockIdx.x;
    int f = threadIdx.x;                   // 256
    int node = g_ti[b];
    float v = (f < GG) ? g_hc[(size_t)g_sidx[node] * GG + f]
                       : g_h2[(size_t)node * GG + (f - GG)];
    g_tgt[((size_t)t * BB + b) * (2 * GG) + f] = v;
}

__global__ void k_zero_h0() {
    int i = blockIdx.x * blockDim.x + threadIdx.x;
    if (i < BB * HH) g_gruh[i] = 0.f;
}

// ------------------------- GRU pointwise -------------------------
__device__ __forceinline__ float sigmoidf_(float x) { return 1.f / (1.f + expf(-x)); }

__global__ void k_gru_pt(int t) {
    int idx = blockIdx.x * blockDim.x + threadIdx.x;
    if (idx >= BB * HH) return;
    int b = idx >> 7, j = idx & 127;
    size_t gir = ((size_t)t * BB + b) * 384;
    size_t ghr = (size_t)b * 384;
    float hr = g_gh[ghr + j], hz = g_gh[ghr + 128 + j], hg = g_gh[ghr + 256 + j];
    float h = g_gruh[idx];
    float r = sigmoidf_(g_gi[gir + j] + hr);
    float z = sigmoidf_(g_gi[gir + 128 + j] + hz);
    float g = tanhf(g_gi[gir + 256 + j] + r * hg);
    float hn = (1.f - z) * g + z * h;
    g_gruh[idx] = hn;
    g_outs[(size_t)t * BB * HH + idx] = hn;
}

// ------------------------- attention + prediction head -------------------------
__global__ void k_final(const float* __restrict__ attn_w, const float* __restrict__ attn_b,
                        const float* __restrict__ pw1, const float* __restrict__ pb1,
                        const float* __restrict__ pw2, const float* __restrict__ pb2,
                        float* __restrict__ out)
{
    int b = blockIdx.x;
    int j = threadIdx.x;                   // 128
    __shared__ float so[TT][HH];
    __shared__ float red[HH];
    __shared__ float sc[TT];
    __shared__ float w8[TT];
    __shared__ float hm[16];

#pragma unroll
    for (int t = 0; t < TT; t++) so[t][j] = g_outs[((size_t)t * BB + b) * HH + j];
    float aw = attn_w[j];
    __syncthreads();

    for (int t = 0; t < TT; t++) {
        red[j] = so[t][j] * aw;
        __syncthreads();
        for (int off = 64; off > 0; off >>= 1) {
            if (j < off) red[j] += red[j + off];
            __syncthreads();
        }
        if (j == 0) sc[t] = tanhf(red[0] + attn_b[0]);
        __syncthreads();
    }
    if (j == 0) {
        float mx = sc[0];
        for (int t = 1; t < TT; t++) mx = fmaxf(mx, sc[t]);
        float s = 0.f;
        for (int t = 0; t < TT; t++) { w8[t] = expf(sc[t] - mx); s += w8[t]; }
        float inv = 1.f / s;
        for (int t = 0; t < TT; t++) w8[t] *= inv;
    }
    __syncthreads();
    float rep = 0.f;
#pragma unroll
    for (int t = 0; t < TT; t++) rep = fmaf(w8[t], so[t][j], rep);
    red[j] = rep;
    __syncthreads();
    if (j < 16) {
        float s = pb1[j];
        for (int k = 0; k < HH; k++) s = fmaf(red[k], pw1[k * 16 + j], s);
        hm[j] = fmaxf(s, 0.f);
    }
    __syncthreads();
    if (j == 0) {
        float p = pb2[0];
#pragma unroll
        for (int k = 0; k < 16; k++) p = fmaf(hm[k], pw2[k], p);
        out[b] = p;
    }
    if (j < TT) out[BB + b * TT + j] = w8[j];
}

// ------------------------- launch -------------------------
extern "C" void kernel_launch(void* const* d_in, const int* in_sizes, int n_in,
                              void* d_out, int out_size)
{
    const float* x       = (const float*)d_in[0];
    const void*  ei      = d_in[1];
    const void*  ti      = d_in[2];
    const float* proj_w  = (const float*)d_in[3];
    const float* proj_b  = (const float*)d_in[4];
    const float* gcn_w1  = (const float*)d_in[5];
    const float* gcn_b1  = (const float*)d_in[6];
    const float* gcn_w2  = (const float*)d_in[7];
    const float* gcn_b2  = (const float*)d_in[8];
    const float* gru_w_ih = (const float*)d_in[9];
    const float* gru_w_hh = (const float*)d_in[10];
    const float* gru_b_ih = (const float*)d_in[11];
    const float* gru_b_hh = (const float*)d_in[12];
    const float* attn_w  = (const float*)d_in[13];
    const float* attn_b  = (const float*)d_in[14];
    const float* pred_w1 = (const float*)d_in[15];
    const float* pred_b1 = (const float*)d_in[16];
    const float* pred_w2 = (const float*)d_in[17];
    const float* pred_b2 = (const float*)d_in[18];
    float* out = (float*)d_out;

    // dynamic smem opt-in for the B panels (idempotent host attribute calls)
    const int SM128 = 128 * 128 * 4;   // 64 KB
    const int SM256 = 256 * 128 * 4;   // 128 KB
    cudaFuncSetAttribute(tfgemm<256, 0, 1, 0, true,  true >, cudaFuncAttributeMaxDynamicSharedMemorySize, SM256);
    cudaFuncSetAttribute(tfgemm<128, 1, 2, 0, false, false>, cudaFuncAttributeMaxDynamicSharedMemorySize, SM128);
    cudaFuncSetAttribute(tfgemm<128, 2, 3, 1, false, false>, cudaFuncAttributeMaxDynamicSharedMemorySize, SM128);
    cudaFuncSetAttribute(tfgemm<256, 3, 4, 0, false, true >, cudaFuncAttributeMaxDynamicSharedMemorySize, SM256);
    cudaFuncSetAttribute(tfgemm<128, 4, 5, 0, false, true >, cudaFuncAttributeMaxDynamicSharedMemorySize, SM128);

    dim3 g313(1, (NNODE + 127) / 128);
    dim3 gGi(3, (TT * BB + 127) / 128);
    dim3 gGru(3, (BB + 127) / 128);
    const int aggBlocks = (NNODE * 32 + 255) / 256;
    const int agg2Blocks = (BB * 32 + 255) / 256;

    // weight prep + index conversion
    k_permB<false><<<(256 * 128 + 255) / 256, 256>>>(proj_w, g_pw, 256, 128);
    k_permB<false><<<(128 * 128 + 255) / 256, 256>>>(gcn_w1, g_pw1, 128, 128);
    k_detect<<<1, 1024>>>((const unsigned int*)ei, BB);
    k_cvt_ti<<<(BB + 255) / 256, 256>>>(ti);
    k_cvt_edges<<<(NE + 255) / 256, 256>>>(ei);
    // big GEMMs for t=0 placed at launch indices 5,6 (ncu -s 5 captures one)
    tfgemm<256, 0, 1, 0, true, true><<<g313, 256, SM256>>>(x, g_pw, proj_b, NNODE);
    tfgemm<128, 1, 2, 0, false, false><<<g313, 256, SM128>>>(nullptr, g_pw1, nullptr, NNODE);

    // remaining preprocessing
    k_permB<false><<<(128 * 128 + 255) / 256, 256>>>(gcn_w2, g_pw2, 128, 128);
    k_permB<true><<<(256 * 384 + 255) / 256, 256>>>(gru_w_ih, g_pwih, 256, 384);
    k_permB<true><<<(128 * 384 + 255) / 256, 256>>>(gru_w_hh, g_pwhh, 128, 384);
    k_init_deg<<<(NNODE + 255) / 256, 256>>>();
    k_deg_edges<<<(NE + 255) / 256, 256>>>();
    k_dinv<<<(NNODE + 255) / 256, 256>>>();
    k_scan<<<1, 1024>>>();
    k_selfloop<<<(NNODE + 255) / 256, 256>>>();
    k_fill_edges<<<(NE + 255) / 256, 256>>>();
    k_clear_masks<<<(NNODE + 255) / 256, 256>>>();
    k_mark_t<<<(BB + 255) / 256, 256>>>();
    k_mark_s<<<(NE + 255) / 256, 256>>>();
    k_mark_s2<<<(NNODE + 255) / 256, 256>>>();
    k_compact<<<(NNODE + 255) / 256, 256>>>();
    k_zero_h0<<<(BB * HH + 255) / 256, 256>>>();

    for (int t = 0; t < TT; t++) {
        if (t > 0) {
            const float* xt = x + (size_t)t * NNODE * FF;
            tfgemm<256, 0, 1, 0, true, true><<<g313, 256, SM256>>>(xt, g_pw, proj_b, NNODE);
            tfgemm<128, 1, 2, 0, false, false><<<g313, 256, SM128>>>(nullptr, g_pw1, nullptr, NNODE);
        }
        // h1 at S nodes only (compact hc)
        k_agg1c<<<aggBlocks, 256>>>(gcn_b1);
        // mc = hc @ gcn_w2 (Ns rows)
        tfgemm<128, 2, 3, 1, false, false><<<g313, 256, SM128>>>(nullptr, g_pw2, nullptr, 0);
        // h2 at target nodes only
        k_agg2t<<<agg2Blocks, 256>>>(gcn_b2);
        // gather targets into tgt[t]
        k_gather<<<BB, 256>>>(t);
    }

    // GI = tgt (8192 x 256) @ wih^T (256 x 384) + b_ih
    tfgemm<256, 3, 4, 0, false, true><<<gGi, 256, SM256>>>(nullptr, g_pwih, gru_b_ih, TT * BB);

    for (int t = 0; t < TT; t++) {
        // Gh = h @ whh^T + b_hh  (1024 x 384)
        tfgemm<128, 4, 5, 0, false, true><<<gGru, 256, SM128>>>(nullptr, g_pwhh, gru_b_hh, BB);
        k_gru_pt<<<(BB * HH + 255) / 256, 256>>>(t);
    }

    k_final<<<BB, HH>>>(attn_w, attn_b, pred_w1, pred_b1, pred_w2, pred_b2, out);
}

// round 7
// speedup vs baseline: 1.7768x; 1.7768x over previous
#include <cuda_runtime.h>
#include <cuda_bf16.h>
#include <math.h>

#define TT 8
#define NNODE 40000
#define FF 256
#define PP 128
#define GG 128
#define HH 128
#define BB 1024
#define NE 640000
#define NNZ (NE + NNODE)

// ------------------------- device scratch -------------------------
__device__ __align__(16) float g_h  [(size_t)NNODE * PP];
__device__ __align__(16) float g_m  [(size_t)NNODE * GG];
__device__ __align__(16) float g_h2 [(size_t)NNODE * GG];
__device__ __align__(16) float g_hc [(size_t)NNODE * GG];
__device__ __align__(16) float g_mc [(size_t)NNODE * GG];
__device__ __align__(16) float g_tgt[(size_t)TT * BB * (2 * GG)];
__device__ __align__(16) float g_gi [(size_t)TT * BB * (3 * HH)];
__device__ __align__(16) float g_gh [(size_t)BB * (3 * HH)];
__device__ __align__(16) float g_wihT[(size_t)(2 * GG) * (3 * HH)];   // 256 x 384
__device__ __align__(16) float g_whhT[(size_t)HH * (3 * HH)];         // 128 x 384
__device__ __align__(16) float g_gruh[(size_t)BB * HH];
__device__ __align__(16) float g_outs[(size_t)TT * BB * HH];
__device__ __align__(16) float g_val [NNZ];
__device__ __align__(16) float g_dinv[NNODE];
__device__ __align__(16) int   g_col [NNZ];
__device__ __align__(16) int   g_rowptr[NNODE + 1];
__device__ __align__(16) int   g_deg [NNODE];
__device__ __align__(16) int   g_fill[NNODE];
__device__ __align__(16) int   g_src [NE];
__device__ __align__(16) int   g_dst [NE];
__device__ __align__(16) int   g_ti  [BB];
// pruning structures
__device__ __align__(16) int   g_tmask[NNODE];
__device__ __align__(16) int   g_smask[NNODE];
__device__ __align__(16) int   g_snodes[NNODE];
__device__ __align__(16) int   g_sidx [NNODE];
__device__ __align__(16) int   g_tnodes[BB];
__device__ int g_nt;
__device__ int g_ns;
__device__ int g_is64;

// ------------------------- index dtype detection + conversion -------------------------
__global__ void k_detect(const unsigned int* __restrict__ wdata, int n_elems) {
    __shared__ int bad;
    if (threadIdx.x == 0) bad = 0;
    __syncthreads();
    int limit = n_elems < 4096 ? n_elems : 4096;
    for (int i = threadIdx.x; i < limit; i += blockDim.x)
        if (wdata[2 * i + 1] != 0u) bad = 1;
    __syncthreads();
    if (threadIdx.x == 0) g_is64 = bad ? 0 : 1;
}

__device__ __forceinline__ int clampN(int v) {
    return v < 0 ? 0 : (v >= NNODE ? NNODE - 1 : v);
}

__global__ void k_cvt_edges(const void* __restrict__ ei) {
    int e = blockIdx.x * blockDim.x + threadIdx.x;
    if (e < NE) {
        int s, d;
        if (g_is64) {
            const long long* p = (const long long*)ei;
            s = (int)p[e]; d = (int)p[NE + e];
        } else {
            const int* p = (const int*)ei;
            s = p[e]; d = p[NE + e];
        }
        g_src[e] = clampN(s);
        g_dst[e] = clampN(d);
    }
}

__global__ void k_cvt_ti(const void* __restrict__ ti) {
    int b = blockIdx.x * blockDim.x + threadIdx.x;
    if (b < BB) {
        int v;
        if (g_is64) v = (int)((const long long*)ti)[b];
        else        v = ((const int*)ti)[b];
        g_ti[b] = clampN(v);
    }
}

// ------------------------- SGEMM (128x128x16 tile, 8x8/thread) -------------------------
// AS: 0 ext, 1 g_h, 2 g_hc, 3 g_tgt, 4 g_gruh
// BS: 0 ext, 1 g_wihT, 2 g_whhT
// CS: 1 g_h, 2 g_m, 3 g_mc, 4 g_gi, 5 g_gh
// MSEL: 0 param M, 1 g_ns
template<int AS, int BS, int CS, int MSEL, bool RELU, bool BIAS>
__global__ void sgemm128(const float* __restrict__ Aext,
                         const float* __restrict__ Bext,
                         const float* __restrict__ bias,
                         int Mparam, int N, int K)
{
    int M = (MSEL == 1) ? g_ns : Mparam;
    int rowBase = blockIdx.y * 128;
    if (rowBase >= M) return;

    const float* A;
    if constexpr (AS == 1)      A = g_h;
    else if constexpr (AS == 2) A = g_hc;
    else if constexpr (AS == 3) A = g_tgt;
    else if constexpr (AS == 4) A = g_gruh;
    else                        A = Aext;
    const float* B;
    if constexpr (BS == 1)      B = g_wihT;
    else if constexpr (BS == 2) B = g_whhT;
    else                        B = Bext;
    float* C;
    if constexpr (CS == 1)      C = g_h;
    else if constexpr (CS == 2) C = g_m;
    else if constexpr (CS == 3) C = g_mc;
    else if constexpr (CS == 4) C = g_gi;
    else                        C = g_gh;

    const int BM = 128, BN = 128, BK = 16, TM = 8, TN = 8;
    __shared__ __align__(16) float As[BK][BM];
    __shared__ __align__(16) float Bs[BK][BN];
    int tid = threadIdx.x;                 // 256 threads
    int tx = tid % 16, ty = tid / 16;
    int colBase = blockIdx.x * BN;

    float acc[TM][TN];
#pragma unroll
    for (int i = 0; i < TM; i++)
#pragma unroll
        for (int j = 0; j < TN; j++) acc[i][j] = 0.f;

    int aRow = tid >> 2;                   // 0..63
    int aCol = (tid & 3) * 4;              // 0,4,8,12
    int bRow = tid >> 5;                   // 0..7
    int bCol = (tid & 31) * 4;             // 0..124

    for (int k0 = 0; k0 < K; k0 += BK) {
#pragma unroll
        for (int p = 0; p < 2; p++) {
            int r = aRow + p * 64;
            int gr = rowBase + r;
            float4 v = make_float4(0.f, 0.f, 0.f, 0.f);
            if (gr < M) v = *(const float4*)(A + (size_t)gr * K + k0 + aCol);
            As[aCol + 0][r] = v.x; As[aCol + 1][r] = v.y;
            As[aCol + 2][r] = v.z; As[aCol + 3][r] = v.w;
        }
#pragma unroll
        for (int p = 0; p < 2; p++) {
            int r = bRow + p * 8;
            float4 v = *(const float4*)(B + (size_t)(k0 + r) * N + colBase + bCol);
            *(float4*)&Bs[r][bCol] = v;
        }
        __syncthreads();
#pragma unroll
        for (int kk = 0; kk < BK; kk++) {
            float a[TM], b[TN];
#pragma unroll
            for (int i = 0; i < TM; i++) a[i] = As[kk][ty * TM + i];
#pragma unroll
            for (int j = 0; j < TN; j++) b[j] = Bs[kk][tx * TN + j];
#pragma unroll
            for (int i = 0; i < TM; i++)
#pragma unroll
                for (int j = 0; j < TN; j++) acc[i][j] = fmaf(a[i], b[j], acc[i][j]);
        }
        __syncthreads();
    }

#pragma unroll
    for (int i = 0; i < TM; i++) {
        int gr = rowBase + ty * TM + i;
        if (gr >= M) continue;
#pragma unroll
        for (int j = 0; j < TN; j += 4) {
            int gc = colBase + tx * TN + j;
            float4 o;
            o.x = acc[i][j]; o.y = acc[i][j + 1]; o.z = acc[i][j + 2]; o.w = acc[i][j + 3];
            if (BIAS) {
                o.x += bias[gc]; o.y += bias[gc + 1]; o.z += bias[gc + 2]; o.w += bias[gc + 3];
            }
            if (RELU) {
                o.x = fmaxf(o.x, 0.f); o.y = fmaxf(o.y, 0.f);
                o.z = fmaxf(o.z, 0.f); o.w = fmaxf(o.w, 0.f);
            }
            *(float4*)(C + (size_t)gr * N + gc) = o;
        }
    }
}

// ------------------------- graph preprocessing -------------------------
__global__ void k_init_deg() {
    int i = blockIdx.x * blockDim.x + threadIdx.x;
    if (i < NNODE) { g_deg[i] = 1; g_fill[i] = 0; }
    if (i == 0) { g_nt = 0; g_ns = 0; }
}

__global__ void k_deg_edges() {
    int e = blockIdx.x * blockDim.x + threadIdx.x;
    if (e < NE) atomicAdd(&g_deg[g_dst[e]], 1);
}

__global__ void k_dinv() {
    int i = blockIdx.x * blockDim.x + threadIdx.x;
    if (i < NNODE) g_dinv[i] = rsqrtf((float)g_deg[i]);
}

__global__ void k_scan() {
    const int CH = 40;
    int t = threadIdx.x;
    int lane = t & 31, wid = t >> 5;
    int beg = t * CH;
    int sum = 0;
    for (int i = 0; i < CH; i++) {
        int idx = beg + i;
        if (idx < NNODE) sum += g_deg[idx];
    }
    int v = sum;
    for (int o = 1; o < 32; o <<= 1) {
        int u = __shfl_up_sync(0xffffffffu, v, o);
        if (lane >= o) v += u;
    }
    __shared__ int wsum[32];
    if (lane == 31) wsum[wid] = v;
    __syncthreads();
    if (wid == 0) {
        int w = wsum[lane];
        for (int o = 1; o < 32; o <<= 1) {
            int u = __shfl_up_sync(0xffffffffu, w, o);
            if (lane >= o) w += u;
        }
        wsum[lane] = w;
    }
    __syncthreads();
    int run = v - sum + (wid > 0 ? wsum[wid - 1] : 0);
    for (int i = 0; i < CH; i++) {
        int idx = beg + i;
        if (idx < NNODE) {
            g_rowptr[idx] = run;
            run += g_deg[idx];
        }
    }
    if (t == 1023) g_rowptr[NNODE] = run;
}

__global__ void k_selfloop() {
    int n = blockIdx.x * blockDim.x + threadIdx.x;
    if (n < NNODE) {
        int pos = g_rowptr[n];
        g_col[pos] = n;
        float d = g_dinv[n];
        g_val[pos] = d * d;
        g_fill[n] = 1;
    }
}

__global__ void k_fill_edges() {
    int e = blockIdx.x * blockDim.x + threadIdx.x;
    if (e < NE) {
        int s = g_src[e];
        int d = g_dst[e];
        int pos = g_rowptr[d] + atomicAdd(&g_fill[d], 1);
        g_col[pos] = s;
        g_val[pos] = g_dinv[s] * g_dinv[d];
    }
}

// ------------------------- target-neighborhood compaction -------------------------
__global__ void k_clear_masks() {
    int i = blockIdx.x * blockDim.x + threadIdx.x;
    if (i < NNODE) { g_tmask[i] = 0; g_smask[i] = 0; }
}
__global__ void k_mark_t() {
    int b = blockIdx.x * blockDim.x + threadIdx.x;
    if (b < BB) g_tmask[g_ti[b]] = 1;
}
__global__ void k_mark_s() {
    int e = blockIdx.x * blockDim.x + threadIdx.x;
    if (e < NE && g_tmask[g_dst[e]]) g_smask[g_src[e]] = 1;
}
__global__ void k_mark_s2() {
    int n = blockIdx.x * blockDim.x + threadIdx.x;
    if (n < NNODE && g_tmask[n]) g_smask[n] = 1;
}
__global__ void k_compact() {
    int n = blockIdx.x * blockDim.x + threadIdx.x;
    if (n < NNODE) {
        if (g_tmask[n]) g_tnodes[atomicAdd(&g_nt, 1)] = n;
        if (g_smask[n]) {
            int ix = atomicAdd(&g_ns, 1);
            g_snodes[ix] = n;
            g_sidx[n] = ix;
        }
    }
}

// ------------------------- GCN layer-1 aggregation at S nodes only -------------------------
__global__ void k_agg1c(const float* __restrict__ bias)
{
    int warp = (blockIdx.x * blockDim.x + threadIdx.x) >> 5;
    int lane = threadIdx.x & 31;
    if (warp >= g_ns) return;
    int node = g_snodes[warp];
    int s0 = g_rowptr[node], s1 = g_rowptr[node + 1];
    const float4* m4 = (const float4*)g_m;
    float4 acc = make_float4(0.f, 0.f, 0.f, 0.f);
    for (int e = s0; e < s1; e++) {
        float v = g_val[e];
        float4 t = m4[(size_t)g_col[e] * 32 + lane];
        acc.x = fmaf(v, t.x, acc.x); acc.y = fmaf(v, t.y, acc.y);
        acc.z = fmaf(v, t.z, acc.z); acc.w = fmaf(v, t.w, acc.w);
    }
    int c = lane * 4;
    acc.x = fmaxf(acc.x + bias[c + 0], 0.f);
    acc.y = fmaxf(acc.y + bias[c + 1], 0.f);
    acc.z = fmaxf(acc.z + bias[c + 2], 0.f);
    acc.w = fmaxf(acc.w + bias[c + 3], 0.f);
    ((float4*)g_hc)[(size_t)warp * 32 + lane] = acc;     // compact row = s-index
}

// layer-2 aggregation only over unique target nodes (reads compact g_mc)
__global__ void k_agg2t(const float* __restrict__ bias)
{
    int warp = (blockIdx.x * blockDim.x + threadIdx.x) >> 5;
    int lane = threadIdx.x & 31;
    if (warp >= g_nt) return;
    int node = g_tnodes[warp];
    int s0 = g_rowptr[node], s1 = g_rowptr[node + 1];
    const float4* m4 = (const float4*)g_mc;
    float4 acc = make_float4(0.f, 0.f, 0.f, 0.f);
    for (int e = s0; e < s1; e++) {
        float v = g_val[e];
        float4 t = m4[(size_t)g_sidx[g_col[e]] * 32 + lane];
        acc.x = fmaf(v, t.x, acc.x); acc.y = fmaf(v, t.y, acc.y);
        acc.z = fmaf(v, t.z, acc.z); acc.w = fmaf(v, t.w, acc.w);
    }
    int c = lane * 4;
    acc.x = fmaxf(acc.x + bias[c + 0], 0.f);
    acc.y = fmaxf(acc.y + bias[c + 1], 0.f);
    acc.z = fmaxf(acc.z + bias[c + 2], 0.f);
    acc.w = fmaxf(acc.w + bias[c + 3], 0.f);
    ((float4*)g_h2)[(size_t)node * 32 + lane] = acc;
}

// ------------------------- gather targets -------------------------
__global__ void k_gather(int t) {
    int b = blockIdx.x;
    int f = threadIdx.x;                   // 256
    int node = g_ti[b];
    float v = (f < GG) ? g_hc[(size_t)g_sidx[node] * GG + f]
                       : g_h2[(size_t)node * GG + (f - GG)];
    g_tgt[((size_t)t * BB + b) * (2 * GG) + f] = v;
}

// ------------------------- weight transposes / zero -------------------------
__global__ void k_transpose_wih(const float* __restrict__ w) {  // (384,256) -> (256,384)
    int i = blockIdx.x * blockDim.x + threadIdx.x;
    if (i < 384 * 256) {
        int jj = i / 256, k = i % 256;
        g_wihT[(size_t)k * 384 + jj] = w[i];
    }
}
__global__ void k_transpose_whh(const float* __restrict__ w) {  // (384,128) -> (128,384)
    int i = blockIdx.x * blockDim.x + threadIdx.x;
    if (i < 384 * 128) {
        int jj = i / 128, k = i % 128;
        g_whhT[(size_t)k * 384 + jj] = w[i];
    }
}
__global__ void k_zero_h0() {
    int i = blockIdx.x * blockDim.x + threadIdx.x;
    if (i < BB * HH) g_gruh[i] = 0.f;
}

// ------------------------- GRU pointwise -------------------------
__device__ __forceinline__ float sigmoidf_(float x) { return 1.f / (1.f + expf(-x)); }

__global__ void k_gru_pt(int t) {
    int idx = blockIdx.x * blockDim.x + threadIdx.x;
    if (idx >= BB * HH) return;
    int b = idx >> 7, j = idx & 127;
    size_t gir = ((size_t)t * BB + b) * 384;
    size_t ghr = (size_t)b * 384;
    float hr = g_gh[ghr + j], hz = g_gh[ghr + 128 + j], hg = g_gh[ghr + 256 + j];
    float h = g_gruh[idx];
    float r = sigmoidf_(g_gi[gir + j] + hr);
    float z = sigmoidf_(g_gi[gir + 128 + j] + hz);
    float g = tanhf(g_gi[gir + 256 + j] + r * hg);
    float hn = (1.f - z) * g + z * h;
    g_gruh[idx] = hn;
    g_outs[(size_t)t * BB * HH + idx] = hn;
}

// ------------------------- attention + prediction head -------------------------
__global__ void k_final(const float* __restrict__ attn_w, const float* __restrict__ attn_b,
                        const float* __restrict__ pw1, const float* __restrict__ pb1,
                        const float* __restrict__ pw2, const float* __restrict__ pb2,
                        float* __restrict__ out)
{
    int b = blockIdx.x;
    int j = threadIdx.x;                   // 128
    __shared__ float so[TT][HH];
    __shared__ float red[HH];
    __shared__ float sc[TT];
    __shared__ float w8[TT];
    __shared__ float hm[16];

#pragma unroll
    for (int t = 0; t < TT; t++) so[t][j] = g_outs[((size_t)t * BB + b) * HH + j];
    float aw = attn_w[j];
    __syncthreads();

    for (int t = 0; t < TT; t++) {
        red[j] = so[t][j] * aw;
        __syncthreads();
        for (int off = 64; off > 0; off >>= 1) {
            if (j < off) red[j] += red[j + off];
            __syncthreads();
        }
        if (j == 0) sc[t] = tanhf(red[0] + attn_b[0]);
        __syncthreads();
    }
    if (j == 0) {
        float mx = sc[0];
        for (int t = 1; t < TT; t++) mx = fmaxf(mx, sc[t]);
        float s = 0.f;
        for (int t = 0; t < TT; t++) { w8[t] = expf(sc[t] - mx); s += w8[t]; }
        float inv = 1.f / s;
        for (int t = 0; t < TT; t++) w8[t] *= inv;
    }
    __syncthreads();
    float rep = 0.f;
#pragma unroll
    for (int t = 0; t < TT; t++) rep = fmaf(w8[t], so[t][j], rep);
    red[j] = rep;
    __syncthreads();
    if (j < 16) {
        float s = pb1[j];
        for (int k = 0; k < HH; k++) s = fmaf(red[k], pw1[k * 16 + j], s);
        hm[j] = fmaxf(s, 0.f);
    }
    __syncthreads();
    if (j == 0) {
        float p = pb2[0];
#pragma unroll
        for (int k = 0; k < 16; k++) p = fmaf(hm[k], pw2[k], p);
        out[b] = p;
    }
    if (j < TT) out[BB + b * TT + j] = w8[j];
}

// ------------------------- launch -------------------------
extern "C" void kernel_launch(void* const* d_in, const int* in_sizes, int n_in,
                              void* d_out, int out_size)
{
    const float* x       = (const float*)d_in[0];
    const void*  ei      = d_in[1];
    const void*  ti      = d_in[2];
    const float* proj_w  = (const float*)d_in[3];
    const float* proj_b  = (const float*)d_in[4];
    const float* gcn_w1  = (const float*)d_in[5];
    const float* gcn_b1  = (const float*)d_in[6];
    const float* gcn_w2  = (const float*)d_in[7];
    const float* gcn_b2  = (const float*)d_in[8];
    const float* gru_w_ih = (const float*)d_in[9];
    const float* gru_w_hh = (const float*)d_in[10];
    const float* gru_b_ih = (const float*)d_in[11];
    const float* gru_b_hh = (const float*)d_in[12];
    const float* attn_w  = (const float*)d_in[13];
    const float* attn_b  = (const float*)d_in[14];
    const float* pred_w1 = (const float*)d_in[15];
    const float* pred_b1 = (const float*)d_in[16];
    const float* pred_w2 = (const float*)d_in[17];
    const float* pred_b2 = (const float*)d_in[18];
    float* out = (float*)d_out;

    dim3 g313(1, (NNODE + 127) / 128);
    dim3 gGi(3, (TT * BB + 127) / 128);
    dim3 gGru(3, (BB + 127) / 128);
    const int aggBlocks = (NNODE * 32 + 255) / 256;
    const int agg2Blocks = (BB * 32 + 255) / 256;

    // indices 0-4: light preprocessing; index 5: dominant proj GEMM (ncu -s 5)
    k_detect<<<1, 1024>>>((const unsigned int*)ei, BB);                          // 0
    k_cvt_ti<<<(BB + 255) / 256, 256>>>(ti);                                     // 1
    k_cvt_edges<<<(NE + 255) / 256, 256>>>(ei);                                  // 2
    k_transpose_wih<<<(384 * 256 + 255) / 256, 256>>>(gru_w_ih);                 // 3
    k_transpose_whh<<<(384 * 128 + 255) / 256, 256>>>(gru_w_hh);                 // 4
    sgemm128<0, 0, 1, 0, true, true><<<g313, 256>>>(x, proj_w, proj_b, NNODE, PP, FF);      // 5: proj t=0
    sgemm128<1, 0, 2, 0, false, false><<<g313, 256>>>(nullptr, gcn_w1, nullptr, NNODE, GG, PP); // 6: gemm1 t=0

    // remaining preprocessing
    k_init_deg<<<(NNODE + 255) / 256, 256>>>();
    k_deg_edges<<<(NE + 255) / 256, 256>>>();
    k_dinv<<<(NNODE + 255) / 256, 256>>>();
    k_scan<<<1, 1024>>>();
    k_selfloop<<<(NNODE + 255) / 256, 256>>>();
    k_fill_edges<<<(NE + 255) / 256, 256>>>();
    k_clear_masks<<<(NNODE + 255) / 256, 256>>>();
    k_mark_t<<<(BB + 255) / 256, 256>>>();
    k_mark_s<<<(NE + 255) / 256, 256>>>();
    k_mark_s2<<<(NNODE + 255) / 256, 256>>>();
    k_compact<<<(NNODE + 255) / 256, 256>>>();
    k_zero_h0<<<(BB * HH + 255) / 256, 256>>>();

    for (int t = 0; t < TT; t++) {
        if (t > 0) {
            const float* xt = x + (size_t)t * NNODE * FF;
            sgemm128<0, 0, 1, 0, true, true><<<g313, 256>>>(xt, proj_w, proj_b, NNODE, PP, FF);
            sgemm128<1, 0, 2, 0, false, false><<<g313, 256>>>(nullptr, gcn_w1, nullptr, NNODE, GG, PP);
        }
        // h1 at S nodes only -> compact g_hc
        k_agg1c<<<aggBlocks, 256>>>(gcn_b1);
        // mc = hc @ gcn_w2 (Ns rows, dynamic M)
        sgemm128<2, 0, 3, 1, false, false><<<g313, 256>>>(nullptr, gcn_w2, nullptr, 0, GG, GG);
        // h2 at target nodes only
        k_agg2t<<<agg2Blocks, 256>>>(gcn_b2);
        // gather targets into tgt[t]
        k_gather<<<BB, 256>>>(t);
    }

    // GI = tgt (8192 x 256) @ wihT (256 x 384) + b_ih
    sgemm128<3, 1, 4, 0, false, true><<<gGi, 256>>>(nullptr, nullptr, gru_b_ih, TT * BB, 3 * HH, 2 * GG);

    for (int t = 0; t < TT; t++) {
        // Gh = gruh (1024x128) @ whhT (128x384) + b_hh
        sgemm128<4, 2, 5, 0, false, true><<<gGru, 256>>>(nullptr, nullptr, gru_b_hh, BB, 3 * HH, HH);
        k_gru_pt<<<(BB * HH + 255) / 256, 256>>>(t);
    }

    k_final<<<BB, HH>>>(attn_w, attn_b, pred_w1, pred_b1, pred_w2, pred_b2, out);
}